// round 1
// baseline (speedup 1.0000x reference)
#include <cuda_runtime.h>

// SpatialMaxout2d forward, kh=kw=2, H=W=224 (padding windows are fully cropped
// away, so only the 112x112 in-bounds 2x2 windows matter).
//
// Per window (v0,v1,v2,v3 row-major), with a[i] = alpha flat:
//   mx  = max(v)
//   idx = first argmax
//   out[i] = (1-a[i]) * (i==idx ? mx : 0) + a[i]*v[i]
//
// One thread processes a 4-wide x 2-tall patch = two adjacent 2x2 windows,
// via two float4 loads + two float4 stores (coalesced, 16B aligned).

__device__ __forceinline__ void blend_window(
    float v0, float v1, float v2, float v3,
    float a0, float a1, float a2, float a3,
    float& o0, float& o1, float& o2, float& o3)
{
    float mx = fmaxf(fmaxf(v0, v1), fmaxf(v2, v3));
    // first-argmax one-hot (jnp.argmax picks first max)
    bool m0 = (v0 == mx);
    bool m1 = (!m0) && (v1 == mx);
    bool m2 = (!m0) && (!m1) && (v2 == mx);
    bool m3 = (!m0) && (!m1) && (!m2);
    float u0 = m0 ? mx : 0.0f;
    float u1 = m1 ? mx : 0.0f;
    float u2 = m2 ? mx : 0.0f;
    float u3 = m3 ? mx : 0.0f;
    o0 = (1.0f - a0) * u0 + a0 * v0;
    o1 = (1.0f - a1) * u1 + a1 * v1;
    o2 = (1.0f - a2) * u2 + a2 * v2;
    o3 = (1.0f - a3) * u3 + a3 * v3;
}

__global__ void spatial_maxout2d_kernel(
    const float* __restrict__ x,
    const float* __restrict__ alpha,
    float* __restrict__ out,
    int total)   // total quad-tasks = B*C*112*56
{
    int t = blockIdx.x * blockDim.x + threadIdx.x;
    if (t >= total) return;

    const float a0 = __ldg(alpha + 0);
    const float a1 = __ldg(alpha + 1);
    const float a2 = __ldg(alpha + 2);
    const float a3 = __ldg(alpha + 3);

    // Decompose: wq in [0,56) quad-column, r in [0,112) window-row, bc plane
    int wq = t % 56;
    int tmp = t / 56;
    int r = tmp % 112;
    int bc = tmp / 112;

    // element offset of the top-left of this 4-wide patch
    long long base = (long long)bc * (224 * 224) + (long long)(2 * r) * 224 + 4 * wq;

    float4 row0 = *reinterpret_cast<const float4*>(x + base);
    float4 row1 = *reinterpret_cast<const float4*>(x + base + 224);

    float4 o0, o1;

    // window A: cols 0,1
    blend_window(row0.x, row0.y, row1.x, row1.y,
                 a0, a1, a2, a3,
                 o0.x, o0.y, o1.x, o1.y);
    // window B: cols 2,3
    blend_window(row0.z, row0.w, row1.z, row1.w,
                 a0, a1, a2, a3,
                 o0.z, o0.w, o1.z, o1.w);

    *reinterpret_cast<float4*>(out + base) = o0;
    *reinterpret_cast<float4*>(out + base + 224) = o1;
}

extern "C" void kernel_launch(void* const* d_in, const int* in_sizes, int n_in,
                              void* d_out, int out_size)
{
    const float* x     = (const float*)d_in[0];
    const float* alpha = (const float*)d_in[1];
    float* out = (float*)d_out;

    // B*C = 32*64 = 2048 planes; per plane 112 window-rows x 56 quad-cols
    const int total = 2048 * 112 * 56;   // 12,845,056
    const int threads = 256;
    const int blocks = (total + threads - 1) / threads;  // 50176

    spatial_maxout2d_kernel<<<blocks, threads>>>(x, alpha, out, total);
}